// round 1
// baseline (speedup 1.0000x reference)
#include <cuda_runtime.h>
#include <math_constants.h>

#define K_LEN 1024
#define I_LEN 8192
#define DIM   128

// Scratch (alloc-free rule: __device__ globals)
__device__ float g_C[K_LEN * I_LEN];   // 32 MB cost matrix
__device__ float g_k2[K_LEN];
__device__ float g_x2[I_LEN];

// ---------------------------------------------------------------------------
// Kernel 1: squared row norms for both inputs. One warp per row.
// ---------------------------------------------------------------------------
__global__ void norms_kernel(const float* __restrict__ kern,
                             const float* __restrict__ x) {
    int warp = (blockIdx.x * blockDim.x + threadIdx.x) >> 5;
    int lane = threadIdx.x & 31;
    if (warp >= K_LEN + I_LEN) return;
    const float* row = (warp < K_LEN) ? (kern + warp * DIM)
                                      : (x + (warp - K_LEN) * DIM);
    float4 v = ((const float4*)row)[lane];          // 32 lanes * 4 = 128
    float s = v.x * v.x + v.y * v.y + v.z * v.z + v.w * v.w;
#pragma unroll
    for (int off = 16; off; off >>= 1) s += __shfl_xor_sync(0xffffffffu, s, off);
    if (lane == 0) {
        if (warp < K_LEN) g_k2[warp] = s;
        else              g_x2[warp - K_LEN] = s;
    }
}

// ---------------------------------------------------------------------------
// Kernel 2: C[m][n] = max(k2[m] + x2[n] - 2 * <kern_m, x_n>, 0)
// Tiled SGEMM: 64x64 tile, BK=64, 256 threads, 4x4 micro-tile per thread.
// ---------------------------------------------------------------------------
#define BM 64
#define BN 64
#define BK 64

__global__ __launch_bounds__(256) void cost_gemm(const float* __restrict__ A,
                                                 const float* __restrict__ B) {
    __shared__ float As[BK][BM + 4];   // transposed: As[k][m]
    __shared__ float Bs[BK][BN + 4];   // transposed: Bs[k][n]
    const int tx = threadIdx.x & 15;
    const int ty = threadIdx.x >> 4;
    const int m0 = blockIdx.y * BM;
    const int n0 = blockIdx.x * BN;
    const int t  = threadIdx.x;

    float acc[4][4] = {};

    for (int k0 = 0; k0 < DIM; k0 += BK) {
#pragma unroll
        for (int i = 0; i < 4; i++) {
            int idx = t + i * 256;        // 0..1023 over 64 rows x 16 float4
            int row = idx >> 4;
            int c4  = idx & 15;
            float4 va = *(const float4*)(A + (size_t)(m0 + row) * DIM + k0 + c4 * 4);
            As[c4 * 4 + 0][row] = va.x;
            As[c4 * 4 + 1][row] = va.y;
            As[c4 * 4 + 2][row] = va.z;
            As[c4 * 4 + 3][row] = va.w;
            float4 vb = *(const float4*)(B + (size_t)(n0 + row) * DIM + k0 + c4 * 4);
            Bs[c4 * 4 + 0][row] = vb.x;
            Bs[c4 * 4 + 1][row] = vb.y;
            Bs[c4 * 4 + 2][row] = vb.z;
            Bs[c4 * 4 + 3][row] = vb.w;
        }
        __syncthreads();
#pragma unroll 16
        for (int kk = 0; kk < BK; kk++) {
            float a[4], b[4];
            *(float4*)a = *(const float4*)&As[kk][ty * 4];
            *(float4*)b = *(const float4*)&Bs[kk][tx * 4];
#pragma unroll
            for (int i = 0; i < 4; i++)
#pragma unroll
                for (int j = 0; j < 4; j++)
                    acc[i][j] += a[i] * b[j];
        }
        __syncthreads();
    }

#pragma unroll
    for (int i = 0; i < 4; i++) {
        int m = m0 + ty * 4 + i;
        float k2 = g_k2[m];
        float4 outv;
        float* ov = (float*)&outv;
#pragma unroll
        for (int j = 0; j < 4; j++) {
            int n = n0 + tx * 4 + j;
            float cv = k2 + g_x2[n] - 2.0f * acc[i][j];
            ov[j] = fmaxf(cv, 0.0f);
        }
        *(float4*)(g_C + (size_t)m * I_LEN + n0 + tx * 4) = outv;
    }
}

// ---------------------------------------------------------------------------
// Kernel 3: DTW DP via (min,+) scan. Single CTA, 1024 threads, 8 cols/thread.
// Row recurrence: D[j] = min(D[j-1] + c[j], e[j]),
//   e[j] = min(Dprev[j-1], Dprev[j]) + c[j]  (Dprev[-1] = +inf; row 0: = 0)
// Scan operator on (C,E): (C1,E1) ⊕ (C2,E2) = (C1+C2, min(E1+C2, E2)).
// ---------------------------------------------------------------------------
__global__ __launch_bounds__(1024, 1) void dtw_dp(float* __restrict__ out,
                                                  int out_size) {
    __shared__ float sh_bound[1024];
    __shared__ float shC[32];
    __shared__ float shE[32];
    const float INF = CUDART_INF_F;
    const int tid  = threadIdx.x;
    const int lane = tid & 31;
    const int wid  = tid >> 5;

    // defensive zero of any extra output elements (element 0 written at end)
    for (int i = tid; i < out_size; i += 1024)
        if (i > 0) out[i] = 0.0f;

    float Dp[8];
#pragma unroll
    for (int j = 0; j < 8; j++) Dp[j] = INF;
    sh_bound[tid] = INF;

    float c[8];
    {
        const float* crow = g_C + tid * 8;
        float4 v0 = *(const float4*)(crow);
        float4 v1 = *(const float4*)(crow + 4);
        c[0] = v0.x; c[1] = v0.y; c[2] = v0.z; c[3] = v0.w;
        c[4] = v1.x; c[5] = v1.y; c[6] = v1.z; c[7] = v1.w;
    }
    __syncthreads();

    for (int r = 0; r < K_LEN; r++) {
        // e-phase: needs previous row's boundary value from neighbor thread
        float dleft = (tid == 0) ? ((r == 0) ? 0.0f : INF) : sh_bound[tid - 1];
        float e[8];
        e[0] = fminf(dleft, Dp[0]) + c[0];
#pragma unroll
        for (int j = 1; j < 8; j++) e[j] = fminf(Dp[j - 1], Dp[j]) + c[j];

        // prefetch next row's costs (in flight across both scans)
        float4 n0 = make_float4(0.f, 0.f, 0.f, 0.f);
        float4 n1 = n0;
        if (r + 1 < K_LEN) {
            const float* nrow = g_C + (size_t)(r + 1) * I_LEN + tid * 8;
            n0 = *(const float4*)(nrow);
            n1 = *(const float4*)(nrow + 4);
        }

        // local compose over 8 columns
        float Cl = c[0], El = e[0];
#pragma unroll
        for (int j = 1; j < 8; j++) {
            El = fminf(El + c[j], e[j]);
            Cl += c[j];
        }

        // warp-level inclusive scan
#pragma unroll
        for (int off = 1; off < 32; off <<= 1) {
            float Cu = __shfl_up_sync(0xffffffffu, Cl, off);
            float Eu = __shfl_up_sync(0xffffffffu, El, off);
            if (lane >= off) {
                El = fminf(Eu + Cl, El);
                Cl = Cu + Cl;
            }
        }
        if (lane == 31) { shC[wid] = Cl; shE[wid] = El; }
        __syncthreads();

        // cross-warp: every warp redundantly scans the 32 warp partials
        float Cp = shC[lane];
        float Ep = shE[lane];
#pragma unroll
        for (int off = 1; off < 32; off <<= 1) {
            float Cu = __shfl_up_sync(0xffffffffu, Cp, off);
            float Eu = __shfl_up_sync(0xffffffffu, Ep, off);
            if (lane >= off) {
                Ep = fminf(Eu + Cp, Ep);
                Cp = Cu + Cp;
            }
        }
        // exclusive warp prefix for this warp (identity for warp 0)
        float wC = __shfl_sync(0xffffffffu, Cp, (wid - 1) & 31);
        float wE = __shfl_sync(0xffffffffu, Ep, (wid - 1) & 31);
        if (wid == 0) { wC = 0.0f; wE = INF; }

        // exclusive in-warp prefix of own (Cl, El)
        float exC = __shfl_up_sync(0xffffffffu, Cl, 1);
        float exE = __shfl_up_sync(0xffffffffu, El, 1);
        if (lane == 0) { exC = 0.0f; exE = INF; }

        // total exclusive prefix -> incoming D value at column 8*tid - 1
        float D = fminf(wE + exC, exE);

        // apply: regenerate this thread's 8 D values
#pragma unroll
        for (int j = 0; j < 8; j++) {
            D = fminf(D + c[j], e[j]);
            Dp[j] = D;
        }
        sh_bound[tid] = Dp[7];

        c[0] = n0.x; c[1] = n0.y; c[2] = n0.z; c[3] = n0.w;
        c[4] = n1.x; c[5] = n1.y; c[6] = n1.z; c[7] = n1.w;
        __syncthreads();
    }

    if (tid == 1023) out[0] = Dp[7];
}

// ---------------------------------------------------------------------------
extern "C" void kernel_launch(void* const* d_in, const int* in_sizes, int n_in,
                              void* d_out, int out_size) {
    const float* kern = (const float*)d_in[0];
    const float* x    = (const float*)d_in[1];
    // defensive: resolve by element counts in case metadata order differs
    if (n_in >= 2 && in_sizes[0] == I_LEN * DIM && in_sizes[1] == K_LEN * DIM) {
        kern = (const float*)d_in[1];
        x    = (const float*)d_in[0];
    }

    int nwarp_rows = K_LEN + I_LEN;                 // 9216 rows, 1 warp each
    norms_kernel<<<(nwarp_rows + 7) / 8, 256>>>(kern, x);

    dim3 grid(I_LEN / BN, K_LEN / BM);
    cost_gemm<<<grid, 256>>>(kern, x);

    dtw_dp<<<1, 1024>>>((float*)d_out, out_size);
}